// round 6
// baseline (speedup 1.0000x reference)
#include <cuda_runtime.h>
#include <cuda_fp16.h>
#include <cstdint>

// ===========================================================================
// Fused kernel: one CTA per m.
//   out[m,c,p,b] = w1[c,0]*t4[l1,b,c] + w1[c,1]*t4[l2,b,c],
//   t4[l,n,c] = sum_{j,k} x4[m,j,l,n+k-1] * w2[j,k,c],  l1=(p+13)%14, l2=(p+12)%14
// GEMM: rows r = l*14+n (196 -> 13 m16 tiles), cols c (256, two halves of 128),
//       K = kk = k*128+j (384 = 24 k16 steps), mma.sync.m16n8k16 f16->f32.
// All shared accesses outside the GEMM are coalesced/conflict-free via
// stride-197 f32 staging (197 mod 32 = 5, coprime with 32).
// ===========================================================================

__device__ __half g_Bh[256 * 384];   // w2^T fp16: [c][kk], kk = k*128+j

__device__ __forceinline__ uint32_t smem_u32(const void* p) {
    uint32_t a;
    asm("{ .reg .u64 t; cvta.to.shared.u64 t, %1; cvt.u32.u64 %0, t; }" : "=r"(a) : "l"(p));
    return a;
}

// ---------------------------------------------------------------------------
// kB: w2 (128,3,256) f32 -> g_Bh[c][k*128+j] fp16  (one-time, tiny)
// ---------------------------------------------------------------------------
__global__ __launch_bounds__(256) void kB(const float* __restrict__ w2) {
    int i = blockIdx.x * 256 + threadIdx.x;          // 98304 total
    if (i >= 98304) return;
    int c  = i / 384;
    int kk = i - c * 384;
    int k  = kk >> 7;
    int j  = kk & 127;
    g_Bh[i] = __float2half(w2[j * 768 + k * 256 + c]);
}

// ---------------------------------------------------------------------------
// kMain
// ---------------------------------------------------------------------------
static constexpr int XS_STRIDE = 136;   // halves
static constexpr int BS_STRIDE = 392;   // halves
static constexpr int T4_STRIDE = 136;   // halves
static constexpr int SCR_STRIDE = 197;  // floats (conflict-free columns)

static constexpr int XS_OFF  = 0;                     // 225*136*2 = 61200 B
static constexpr int SCR_OFF = 61312;                 // max(Bs 100352, scr 128*197*4=100864)
static constexpr int T4_OFF  = 162176;                // 196*136*2 = 53312 B
static constexpr int SMEM_BYTES = 215488;

__global__ __launch_bounds__(1024, 1) void kMain(const float* __restrict__ x,
                                                 const float* __restrict__ w1,
                                                 float* __restrict__ out) {
    extern __shared__ char smem[];
    __half* xs  = (__half*)(smem + XS_OFF);
    __half* Bs  = (__half*)(smem + SCR_OFF);   // time-shared region:
    float*  scr = (float*)(smem + SCR_OFF);    //   temp transpose / Bs / outbuf
    __half* t4s = (__half*)(smem + T4_OFF);

    const int tid  = threadIdx.x;
    const int m    = blockIdx.x;
    const int wid  = tid >> 5;
    const int lane = tid & 31;

    // ---- zero only the h-pad rows of xs: rows l*16 and l*16+15 (cols 0..127) ----
    {
        uint32_t* xz = (uint32_t*)xs;
        for (int i = tid; i < 28 * 64; i += 1024) {
            int r   = i >> 6;                       // 0..27
            int row = (r >> 1) * 16 + (r & 1) * 15;
            xz[(row * XS_STRIDE) / 2 + (i & 63)] = 0;
        }
    }

    // ---- pass 1: x[m] -> scr[j][lh] f32, fully coalesced both sides ----
    const float* xm = x + (size_t)m * 25088;
    for (int i = tid; i < 25088; i += 1024) {
        int j  = i / 196;
        int lh = i - j * 196;
        scr[j * SCR_STRIDE + lh] = xm[i];
    }
    __syncthreads();

    // ---- pass 2: transpose into xs[l*16+h+1][j], conflict-free LDS columns ----
    for (int i = tid; i < 25088; i += 1024) {
        int j  = i & 127;
        int lh = i >> 7;
        int l  = lh / 14;
        int h  = lh - l * 14;
        xs[(l * 16 + h + 1) * XS_STRIDE + j] = __float2half(scr[j * SCR_STRIDE + lh]);
    }
    __syncthreads();

    // ---- per-warp GEMM task: 26 active warps = 13 m-tiles x 2 n64-groups ----
    const int  task   = wid;
    const bool active = task < 26;
    const int  mt     = active ? (task % 13) : 0;
    const int  ngrp   = active ? (task / 13) : 0;
    const int  cbase  = ngrp * 8;                   // first n8-tile index

    const int  rsel    = lane & 15;
    const int  r_row   = mt * 16 + rsel;
    const bool rvalid  = r_row < 196;
    const int  base_lh = rvalid ? (r_row + 2 * (r_row / 14)) : 222;
    const int  j0pre   = (lane >> 4) << 3;
    const uint32_t xs_base = smem_u32(xs);
    const uint32_t a_pre   = xs_base + (uint32_t)((base_lh * XS_STRIDE + j0pre) * 2);

    const int n_in16 = (((lane >> 4) & 1) << 3) + (lane & 7);
    const int k_half = ((lane >> 3) & 1) << 3;
    const uint32_t bs_base = smem_u32(Bs);
    const uint32_t b_pre   = bs_base +
        (uint32_t)(((cbase * 8 + n_in16) * BS_STRIDE + k_half) * 2);

    float* om = out + (size_t)m * 50176;
    const float2* w1v = (const float2*)w1;

    for (int hc = 0; hc < 2; hc++) {
        // ---- load B half into Bs (overwrites scr; safe: scr consumed) ----
        {
            const uint32_t* src = (const uint32_t*)(g_Bh + hc * 128 * 384);
            for (int i = tid; i < 128 * 192; i += 1024) {
                int c  = i / 192;
                int kw = i - c * 192;
                *(uint32_t*)(Bs + c * BS_STRIDE + kw * 2) = src[i];
            }
        }
        __syncthreads();

        float d[8][4];
        #pragma unroll
        for (int i = 0; i < 8; i++)
            #pragma unroll
            for (int q = 0; q < 4; q++) d[i][q] = 0.f;

        if (active) {
            #pragma unroll 4
            for (int s = 0; s < 24; s++) {
                const int tap = s >> 3;
                uint32_t a_addr = a_pre + (uint32_t)(tap * (XS_STRIDE * 2)
                                                    + (s & 7) * 32);
                uint32_t a0, a1, a2, a3;
                asm volatile("ldmatrix.sync.aligned.m8n8.x4.shared.b16 "
                             "{%0,%1,%2,%3}, [%4];"
                             : "=r"(a0), "=r"(a1), "=r"(a2), "=r"(a3) : "r"(a_addr));
                uint32_t b_addr = b_pre + (uint32_t)(s * 32);
                #pragma unroll
                for (int q = 0; q < 4; q++) {
                    uint32_t b0, b1, b2, b3;
                    asm volatile("ldmatrix.sync.aligned.m8n8.x4.shared.b16 "
                                 "{%0,%1,%2,%3}, [%4];"
                                 : "=r"(b0), "=r"(b1), "=r"(b2), "=r"(b3)
                                 : "r"(b_addr));
                    b_addr += 16u * BS_STRIDE * 2u;
                    asm volatile("mma.sync.aligned.m16n8k16.row.col.f32.f16.f16.f32 "
                                 "{%0,%1,%2,%3}, {%4,%5,%6,%7}, {%8,%9}, {%0,%1,%2,%3};"
                                 : "+f"(d[2*q][0]), "+f"(d[2*q][1]),
                                   "+f"(d[2*q][2]), "+f"(d[2*q][3])
                                 : "r"(a0), "r"(a1), "r"(a2), "r"(a3),
                                   "r"(b0), "r"(b1));
                    asm volatile("mma.sync.aligned.m16n8k16.row.col.f32.f16.f16.f32 "
                                 "{%0,%1,%2,%3}, {%4,%5,%6,%7}, {%8,%9}, {%0,%1,%2,%3};"
                                 : "+f"(d[2*q+1][0]), "+f"(d[2*q+1][1]),
                                   "+f"(d[2*q+1][2]), "+f"(d[2*q+1][3])
                                 : "r"(a0), "r"(a1), "r"(a2), "r"(a3),
                                   "r"(b2), "r"(b3));
                }
            }
        }
        __syncthreads();   // GEMM reads of Bs/xs done

        // ---- store fragments to t4s (fp16) ----
        if (active) {
            const int r0 = mt * 16 + (lane >> 2);
            #pragma unroll
            for (int i = 0; i < 8; i++) {
                const int c0 = (cbase + i) * 8 + (lane & 3) * 2;
                if (r0 < 196)
                    *(__half2*)(t4s + r0 * T4_STRIDE + c0) =
                        __floats2half2_rn(d[i][0], d[i][1]);
                if (r0 + 8 < 196)
                    *(__half2*)(t4s + (r0 + 8) * T4_STRIDE + c0) =
                        __floats2half2_rn(d[i][2], d[i][3]);
            }
        }
        __syncthreads();

        // ---- epilogue pass 1: two-tap combine, write outbuf (over Bs) ----
        // lanes read t4s contiguously over cl; write scr columns (stride 197).
        for (int i = tid; i < 25088; i += 1024) {
            int cl = i & 127;
            int rr = i >> 7;           // output row p*14+b
            int p  = rr / 14;
            int b  = rr - p * 14;
            int l1 = (p == 0) ? 13 : p - 1;
            int l2 = (p < 2) ? p + 12 : p - 2;
            float2 wv = w1v[hc * 128 + cl];
            float v = wv.x * __half2float(t4s[(l1 * 14 + b) * T4_STRIDE + cl])
                    + wv.y * __half2float(t4s[(l2 * 14 + b) * T4_STRIDE + cl]);
            scr[cl * SCR_STRIDE + rr] = v;
        }
        __syncthreads();

        // ---- epilogue pass 2: outbuf -> out, coalesced both sides ----
        float* om2 = om + hc * 25088;
        for (int i = tid; i < 25088; i += 1024) {
            int c  = i / 196;
            int rr = i - c * 196;
            om2[i] = scr[c * SCR_STRIDE + rr];
        }
        __syncthreads();   // before next-hc Bs load overwrites scr
    }
}

// ===========================================================================
extern "C" void kernel_launch(void* const* d_in, const int* in_sizes, int n_in,
                              void* d_out, int out_size) {
    const float* x  = (const float*)d_in[0];   // (1024, 1792, 14)
    const float* w1 = (const float*)d_in[1];   // (256, 2)
    const float* w2 = (const float*)d_in[2];   // (128, 3, 256)
    float* out = (float*)d_out;                // (1024, 256, 14, 14)

    static int attr_done = 0;
    if (!attr_done) {
        cudaFuncSetAttribute(kMain, cudaFuncAttributeMaxDynamicSharedMemorySize,
                             SMEM_BYTES);
        attr_done = 1;
    }

    kB<<<384, 256>>>(w2);
    kMain<<<1024, 1024, SMEM_BYTES>>>(x, w1, out);
}